// round 2
// baseline (speedup 1.0000x reference)
#include <cuda_runtime.h>
#include <stdint.h>
#include <math.h>

#define NTOT    (1<<22)
#define NBANDS  8
#define TPB     256

// scatter config
#define SC_CHUNK 2048
#define SC_NBLK  (NTOT/SC_CHUNK)   /* 2048 */
#define SC_L     (SC_CHUNK/TPB)    /* 8    */

// rank config
#define RG       16
#define RNTHR    (NTOT/RG)         /* 262144 */
#define RNBLK    (RNTHR/TPB)       /* 1024   */

// scan config
#define SEG      4
#define SNSEG    (NTOT/SEG)        /* 1048576 */
#define SNBLK    (SNSEG/TPB)       /* 4096    */

typedef unsigned long long ull;

// ---------------- static device scratch ----------------
__device__ ull    g_key[NTOT];
__device__ float  g_by[NTOT], g_bd[NTOT];
__device__ float4 g_sorted[NTOT];            // {t, amp, y, diag} in merged order
__device__ float2 g_DW[NTOT];
__device__ int    g_bcnt[SC_NBLK*NBANDS];
__device__ int    g_boff[SC_NBLK*NBANDS];
__device__ int    g_base[NBANDS+1];
__device__ float4 g_thrM[SNSEG];
__device__ double g_blkM[SNBLK*4], g_blkMex[SNBLK*4];
__device__ float2 g_thrA[SNSEG];
__device__ double g_blkA[SNBLK*2], g_blkAex[SNBLK*2];
__device__ double g_bsum[SNBLK];
__device__ float  g_amps[NBANDS], g_lags[NBANDS], g_ka, g_kc;

__device__ __forceinline__ unsigned fkey(float f){
    unsigned u = __float_as_uint(f);
    return (u & 0x80000000u) ? ~u : (u | 0x80000000u);
}
__device__ __forceinline__ float unfkey(unsigned k){
    unsigned u = (k & 0x80000000u) ? (k & 0x7fffffffu) : ~k;
    return __uint_as_float(u);
}

__device__ __forceinline__ void mmulD(double r[4], const double n[4], const double o[4]){
    double t0 = n[0]*o[0] + n[1]*o[2];
    double t1 = n[0]*o[1] + n[1]*o[3];
    double t2 = n[2]*o[0] + n[3]*o[2];
    double t3 = n[2]*o[1] + n[3]*o[3];
    double mx = fmax(fmax(fabs(t0),fabs(t1)), fmax(fabs(t2),fabs(t3)));
    double s  = (mx > 0.0) ? 1.0/mx : 1.0;
    r[0]=t0*s; r[1]=t1*s; r[2]=t2*s; r[3]=t3*s;
}

// ---------------- params ----------------
__global__ void k_init(const float* __restrict__ lad, const float* __restrict__ lg,
                       const float* __restrict__ lkp){
    if (threadIdx.x == 0){
        g_amps[0] = 1.f; g_lags[0] = 0.f;
        for (int b = 1; b < NBANDS; b++){
            g_amps[b] = expf(lad[b-1]);
            g_lags[b] = lg[b-1];
        }
        g_ka = expf(lkp[0]);
        g_kc = expf(lkp[1]);
    }
}

// ---------------- stage 1: histogram ----------------
__global__ void k_count(const int* __restrict__ band){
    __shared__ int sc[NBANDS];
    int tid = threadIdx.x;
    if (tid < NBANDS) sc[tid] = 0;
    __syncthreads();
    int cnt[NBANDS];
    #pragma unroll
    for (int b = 0; b < NBANDS; b++) cnt[b] = 0;
    int base = blockIdx.x * SC_CHUNK;
    for (int k = tid; k < SC_CHUNK; k += TPB) cnt[band[base+k]]++;
    #pragma unroll
    for (int b = 0; b < NBANDS; b++) if (cnt[b]) atomicAdd(&sc[b], cnt[b]);
    __syncthreads();
    if (tid < NBANDS) g_bcnt[blockIdx.x*NBANDS + tid] = sc[tid];
}

// global exclusive prefix over band-major (b, blk) counts: 16384 values, 1024 thr x 16
__global__ void k_offsets(){
    __shared__ int ssum[1024];
    int tid = threadIdx.x;
    int v[16];
    int run = 0;
    #pragma unroll
    for (int q = 0; q < 16; q++){
        int m = tid*16 + q;
        int b = m >> 11, blk = m & 2047;
        v[q] = run;
        run += g_bcnt[blk*NBANDS + b];
    }
    ssum[tid] = run;
    __syncthreads();
    for (int off = 1; off < 1024; off <<= 1){
        int pv = (tid >= off) ? ssum[tid-off] : 0;
        __syncthreads();
        ssum[tid] += pv;
        __syncthreads();
    }
    int excl = tid ? ssum[tid-1] : 0;
    #pragma unroll
    for (int q = 0; q < 16; q++){
        int m = tid*16 + q;
        int b = m >> 11, blk = m & 2047;
        int p = excl + v[q];
        g_boff[blk*NBANDS + b] = p;
        if (blk == 0) g_base[b] = p;
    }
    if (tid == 0) g_base[NBANDS] = NTOT;
}

// ---------------- stage 2: stable partition by band (smem-staged) ----------------
__global__ void k_scatter(const float* __restrict__ t, const int* __restrict__ band,
                          const float* __restrict__ y, const float* __restrict__ dg){
    __shared__ float s_t[SC_CHUNK], s_y[SC_CHUNK], s_d[SC_CHUNK];
    __shared__ int   s_b[SC_CHUNK];
    __shared__ int   s_scan[NBANDS*TPB];
    __shared__ float s_lag[NBANDS];
    int tid = threadIdx.x;
    int base = blockIdx.x * SC_CHUNK;
    if (tid < NBANDS) s_lag[tid] = g_lags[tid];
    for (int k = tid; k < SC_CHUNK; k += TPB){
        s_t[k] = t[base+k]; s_y[k] = y[base+k]; s_d[k] = dg[base+k]; s_b[k] = band[base+k];
    }
    __syncthreads();
    int cnt[NBANDS];
    #pragma unroll
    for (int b = 0; b < NBANDS; b++) cnt[b] = 0;
    #pragma unroll
    for (int j = 0; j < SC_L; j++) cnt[s_b[tid*SC_L + j]]++;
    #pragma unroll
    for (int b = 0; b < NBANDS; b++) s_scan[b*TPB + tid] = cnt[b];
    __syncthreads();
    for (int off = 1; off < TPB; off <<= 1){
        int v[NBANDS];
        #pragma unroll
        for (int b = 0; b < NBANDS; b++) v[b] = (tid >= off) ? s_scan[b*TPB + tid - off] : 0;
        __syncthreads();
        #pragma unroll
        for (int b = 0; b < NBANDS; b++) s_scan[b*TPB + tid] += v[b];
        __syncthreads();
    }
    int pos[NBANDS];
    #pragma unroll
    for (int b = 0; b < NBANDS; b++)
        pos[b] = g_boff[blockIdx.x*NBANDS + b] + (tid ? s_scan[b*TPB + tid - 1] : 0);
    #pragma unroll
    for (int j = 0; j < SC_L; j++){
        int li = tid*SC_L + j;
        int b = s_b[li];
        float nt = s_t[li] - s_lag[b];
        ull key = ((ull)fkey(nt) << 32) | (unsigned)(base + li);
        int p = pos[b]++;
        g_key[p] = key;
        g_by[p]  = s_y[li];
        g_bd[p]  = s_d[li];
    }
}

// ---------------- stage 3: grouped merge-rank (interleaved 7-band search + gallop) ----------------
__global__ void k_rank(){
    __shared__ int   sb[NBANDS+1];
    __shared__ float sam[NBANDS];
    int tid = threadIdx.x;
    if (tid < NBANDS+1) sb[tid] = g_base[tid];
    if (tid < NBANDS)   sam[tid] = g_amps[tid];
    __syncthreads();
    int g  = blockIdx.x * TPB + tid;
    int j0 = g * RG;

    int k = 0;
    while (k < RG){
        int j = j0 + k;
        int b = 0;
        #pragma unroll
        for (int q = 1; q < NBANDS; q++) b += (j >= sb[q]);
        int runend = sb[b+1] - j0;
        if (runend > RG) runend = RG;

        ull kmax = __ldg(&g_key[j0 + runend - 1]);
        int lo[NBANDS], hi[NBANDS];
        #pragma unroll
        for (int q = 0; q < NBANDS; q++){
            lo[q] = sb[q];
            hi[q] = (q == b) ? sb[q] : sb[q+1];
        }
        for (int it = 0; it < 21; it++){
            #pragma unroll
            for (int q = 0; q < NBANDS; q++){
                if (lo[q] < hi[q]){
                    int mid = (lo[q] + hi[q]) >> 1;
                    ull v = __ldg(&g_key[mid]);
                    if (v < kmax) lo[q] = mid + 1; else hi[q] = mid;
                }
            }
        }
        int acc = 0;
        #pragma unroll
        for (int q = 0; q < NBANDS; q++) acc += lo[q] - sb[q];
        int pos[NBANDS];
        #pragma unroll
        for (int q = 0; q < NBANDS; q++) pos[q] = lo[q];

        float amp = sam[b];
        for (int kk = runend - 1; kk >= k; kk--){
            ull ck = (kk == runend - 1) ? kmax : __ldg(&g_key[j0 + kk]);
            if (kk < runend - 1){
                #pragma unroll
                for (int q = 0; q < NBANDS; q++){
                    while (pos[q] > sb[q] && __ldg(&g_key[pos[q]-1]) > ck){ pos[q]--; acc--; }
                }
            }
            int rank = (j0 + kk - sb[b]) + acc;
            float4 o;
            o.x = unfkey((unsigned)(ck >> 32));
            o.y = amp;
            o.z = g_by[j0 + kk];
            o.w = g_bd[j0 + kk];
            g_sorted[rank] = o;
        }
        k = runend;
    }
}

// ---------------- stage 4a: S-scan segment reduce (Mobius 2x2) ----------------
__global__ void k_sreduce(){
    int tid = threadIdx.x;
    int s = blockIdx.x * TPB + tid;
    int base = s * SEG;
    float a = g_ka, c = g_kc;
    float4 e[SEG];
    #pragma unroll
    for (int j = 0; j < SEG; j++) e[j] = g_sorted[base + j];
    float tprev = base ? g_sorted[base-1].x : e[0].x;
    float m0=1.f, m1=0.f, m2=0.f, m3=1.f;
    #pragma unroll
    for (int j = 0; j < SEG; j++){
        float dt = e[j].x - tprev;
        tprev = e[j].x;
        float phi2 = expf(-2.f*c*dt);
        float V = e[j].y, U = a*V;
        float A = e[j].w + U*V;
        float e00 = (A - 2.f*U*V)*phi2, e01 = V*V, e10 = -U*U*phi2, e11 = A;
        float r0 = e00*m0 + e01*m2, r1 = e00*m1 + e01*m3;
        float r2 = e10*m0 + e11*m2, r3 = e10*m1 + e11*m3;
        float mx = fmaxf(fmaxf(fabsf(r0),fabsf(r1)), fmaxf(fabsf(r2),fabsf(r3)));
        float sc = (mx > 0.f) ? 1.f/mx : 1.f;
        m0=r0*sc; m1=r1*sc; m2=r2*sc; m3=r3*sc;
    }
    __shared__ double sm[TPB*4];
    sm[tid*4+0]=m0; sm[tid*4+1]=m1; sm[tid*4+2]=m2; sm[tid*4+3]=m3;
    __syncthreads();
    for (int off = 1; off < TPB; off <<= 1){
        double pv[4]; int h = (tid >= off);
        if (h){ for (int q=0;q<4;q++) pv[q] = sm[(tid-off)*4+q]; }
        __syncthreads();
        if (h){
            double cu[4]; for (int q=0;q<4;q++) cu[q] = sm[tid*4+q];
            double r[4]; mmulD(r, cu, pv);
            for (int q=0;q<4;q++) sm[tid*4+q] = r[q];
        }
        __syncthreads();
    }
    float4 ex;
    if (tid == 0){ ex = make_float4(1.f,0.f,0.f,1.f); }
    else { ex = make_float4((float)sm[(tid-1)*4+0],(float)sm[(tid-1)*4+1],
                            (float)sm[(tid-1)*4+2],(float)sm[(tid-1)*4+3]); }
    g_thrM[s] = ex;
    if (tid == TPB-1){ for (int q=0;q<4;q++) g_blkM[blockIdx.x*4+q] = sm[tid*4+q]; }
}

__global__ void k_blkscanM(){
    __shared__ double sm[1024*4];
    int tid = threadIdx.x;
    double cur[4] = {1.0,0.0,0.0,1.0};
    double p0[4],p1[4],p2[4],p3[4];
    double m[4];
    #define LOADM(i) { for(int q=0;q<4;q++) m[q]=g_blkM[(tid*4+(i))*4+q]; }
    LOADM(0); mmulD(p0, m, cur);
    LOADM(1); mmulD(p1, m, p0);
    LOADM(2); mmulD(p2, m, p1);
    LOADM(3); mmulD(p3, m, p2);
    #undef LOADM
    for (int q=0;q<4;q++) sm[tid*4+q] = p3[q];
    __syncthreads();
    for (int off = 1; off < 1024; off <<= 1){
        double pv[4]; int h = (tid >= off);
        if (h){ for (int q=0;q<4;q++) pv[q] = sm[(tid-off)*4+q]; }
        __syncthreads();
        if (h){
            double cu[4]; for (int q=0;q<4;q++) cu[q] = sm[tid*4+q];
            double r[4]; mmulD(r, cu, pv);
            for (int q=0;q<4;q++) sm[tid*4+q] = r[q];
        }
        __syncthreads();
    }
    double ex[4];
    if (tid == 0){ ex[0]=1.0; ex[1]=0.0; ex[2]=0.0; ex[3]=1.0; }
    else { for (int q=0;q<4;q++) ex[q] = sm[(tid-1)*4+q]; }
    double o0[4];
    for (int q=0;q<4;q++) g_blkMex[(tid*4+0)*4+q] = ex[q];
    mmulD(o0, p0, ex); for (int q=0;q<4;q++) g_blkMex[(tid*4+1)*4+q] = o0[q];
    mmulD(o0, p1, ex); for (int q=0;q<4;q++) g_blkMex[(tid*4+2)*4+q] = o0[q];
    mmulD(o0, p2, ex); for (int q=0;q<4;q++) g_blkMex[(tid*4+3)*4+q] = o0[q];
}

// ---------------- stage 4b: apply S, emit D/W, build f-affine segments ----------------
__global__ void k_sapply(){
    int tid = threadIdx.x;
    int s = blockIdx.x * TPB + tid;
    int base = s * SEG;
    float4 Ptf = g_thrM[s];
    double Pt[4] = {(double)Ptf.x,(double)Ptf.y,(double)Ptf.z,(double)Ptf.w};
    double Pb[4];
    for (int q=0;q<4;q++) Pb[q] = g_blkMex[blockIdx.x*4+q];
    double E[4]; mmulD(E, Pt, Pb);
    float Sp = (float)(E[1] / E[3]);

    float a = g_ka, c = g_kc;
    float4 e[SEG];
    #pragma unroll
    for (int j = 0; j < SEG; j++) e[j] = g_sorted[base + j];
    float tprev = base ? g_sorted[base-1].x : e[0].x;
    float al = 1.f, be = 0.f;
    #pragma unroll
    for (int j = 0; j < SEG; j++){
        float dt = e[j].x - tprev;
        tprev = e[j].x;
        float phi = expf(-c*dt);
        float phi2 = phi*phi;
        float V = e[j].y, U = a*V;
        float A = e[j].w + U*V;
        float S = phi2 * Sp;
        float D = A - U*U*S;
        float W = (V - U*S) / D;
        g_DW[base+j] = make_float2(D, W);
        float an = phi * (1.f - W*U);
        float bn = W * e[j].z;
        be = an*be + bn;
        al *= an;
        Sp = S + D*W*W;
    }
    __shared__ double sa[TPB*2];
    sa[tid*2] = (double)al; sa[tid*2+1] = (double)be;
    __syncthreads();
    for (int off = 1; off < TPB; off <<= 1){
        double pa=0.0, pb=0.0; int h = (tid >= off);
        if (h){ pa = sa[(tid-off)*2]; pb = sa[(tid-off)*2+1]; }
        __syncthreads();
        if (h){
            double ca = sa[tid*2], cb = sa[tid*2+1];
            sa[tid*2] = ca*pa; sa[tid*2+1] = ca*pb + cb;
        }
        __syncthreads();
    }
    if (tid == 0) g_thrA[s] = make_float2(1.f, 0.f);
    else          g_thrA[s] = make_float2((float)sa[(tid-1)*2], (float)sa[(tid-1)*2+1]);
    if (tid == TPB-1){ g_blkA[blockIdx.x*2] = sa[tid*2]; g_blkA[blockIdx.x*2+1] = sa[tid*2+1]; }
}

__global__ void k_blkscanA(){
    __shared__ double sa[1024*2];
    int tid = threadIdx.x;
    double pa0,pb0,pa1,pb1,pa2,pb2,pa3,pb3;
    {
        double ca = g_blkA[(tid*4+0)*2], cb = g_blkA[(tid*4+0)*2+1];
        pa0 = ca; pb0 = cb;
        ca = g_blkA[(tid*4+1)*2]; cb = g_blkA[(tid*4+1)*2+1];
        pa1 = ca*pa0; pb1 = ca*pb0 + cb;
        ca = g_blkA[(tid*4+2)*2]; cb = g_blkA[(tid*4+2)*2+1];
        pa2 = ca*pa1; pb2 = ca*pb1 + cb;
        ca = g_blkA[(tid*4+3)*2]; cb = g_blkA[(tid*4+3)*2+1];
        pa3 = ca*pa2; pb3 = ca*pb2 + cb;
    }
    sa[tid*2] = pa3; sa[tid*2+1] = pb3;
    __syncthreads();
    for (int off = 1; off < 1024; off <<= 1){
        double pa=0.0, pb=0.0; int h = (tid >= off);
        if (h){ pa = sa[(tid-off)*2]; pb = sa[(tid-off)*2+1]; }
        __syncthreads();
        if (h){
            double ca = sa[tid*2], cb = sa[tid*2+1];
            sa[tid*2] = ca*pa; sa[tid*2+1] = ca*pb + cb;
        }
        __syncthreads();
    }
    double exa, exb;
    if (tid == 0){ exa = 1.0; exb = 0.0; }
    else { exa = sa[(tid-1)*2]; exb = sa[(tid-1)*2+1]; }
    g_blkAex[(tid*4+0)*2] = exa;        g_blkAex[(tid*4+0)*2+1] = exb;
    g_blkAex[(tid*4+1)*2] = pa0*exa;    g_blkAex[(tid*4+1)*2+1] = pa0*exb + pb0;
    g_blkAex[(tid*4+2)*2] = pa1*exa;    g_blkAex[(tid*4+2)*2+1] = pa1*exb + pb1;
    g_blkAex[(tid*4+3)*2] = pa2*exa;    g_blkAex[(tid*4+3)*2+1] = pa2*exb + pb2;
}

// ---------------- stage 4c: apply f, compute z, reduce ----------------
__global__ void k_fapply(){
    int tid = threadIdx.x;
    int s = blockIdx.x * TPB + tid;
    int base = s * SEG;
    float2 ta = g_thrA[s];
    float fb = (float)g_blkAex[blockIdx.x*2+1];
    float f = ta.x * fb + ta.y;
    float a = g_ka, c = g_kc;
    float4 e[SEG];
    #pragma unroll
    for (int j = 0; j < SEG; j++) e[j] = g_sorted[base + j];
    float2 dw[SEG];
    #pragma unroll
    for (int j = 0; j < SEG; j++) dw[j] = g_DW[base + j];
    float tprev = base ? g_sorted[base-1].x : e[0].x;
    double loc = 0.0;
    #pragma unroll
    for (int j = 0; j < SEG; j++){
        float dt = e[j].x - tprev;
        tprev = e[j].x;
        float phi = expf(-c*dt);
        float U = a * e[j].y;
        float fin = phi * f;
        float z = e[j].z - U * fin;
        f = fin + dw[j].y * z;
        loc += (double)(z*z / dw[j].x) + (double)logf(dw[j].x);
    }
    __shared__ double red[TPB];
    red[tid] = loc;
    __syncthreads();
    for (int off = TPB/2; off > 0; off >>= 1){
        if (tid < off) red[tid] += red[tid+off];
        __syncthreads();
    }
    if (tid == 0) g_bsum[blockIdx.x] = red[0];
}

__global__ void k_final(float* out){
    __shared__ double red[1024];
    int tid = threadIdx.x;
    double s = 0.0;
    #pragma unroll
    for (int q = 0; q < 4; q++) s += g_bsum[tid*4 + q];
    red[tid] = s;
    __syncthreads();
    for (int off = 512; off > 0; off >>= 1){
        if (tid < off) red[tid] += red[tid+off];
        __syncthreads();
    }
    if (tid == 0) out[0] = (float)(0.5 * (red[0] + (double)NTOT * 1.8378770664093454));
}

// ---------------- launch ----------------
extern "C" void kernel_launch(void* const* d_in, const int* in_sizes, int n_in,
                              void* d_out, int out_size){
    const float* t    = (const float*)d_in[0];
    const int*   band = (const int*)  d_in[1];
    const float* y    = (const float*)d_in[2];
    const float* dg   = (const float*)d_in[3];
    const float* lad  = (const float*)d_in[4];
    const float* lg   = (const float*)d_in[5];
    const float* lkp  = (const float*)d_in[6];
    float* out = (float*)d_out;

    k_init    <<<1, 32>>>(lad, lg, lkp);
    k_count   <<<SC_NBLK, TPB>>>(band);
    k_offsets <<<1, 1024>>>();
    k_scatter <<<SC_NBLK, TPB>>>(t, band, y, dg);
    k_rank    <<<RNBLK, TPB>>>();
    k_sreduce <<<SNBLK, TPB>>>();
    k_blkscanM<<<1, 1024>>>();
    k_sapply  <<<SNBLK, TPB>>>();
    k_blkscanA<<<1, 1024>>>();
    k_fapply  <<<SNBLK, TPB>>>();
    k_final   <<<1, 1024>>>(out);
}

// round 3
// speedup vs baseline: 1.4117x; 1.4117x over previous
#include <cuda_runtime.h>
#include <stdint.h>
#include <math.h>

#define NTOT    (1<<22)
#define NBANDS  8
#define TPB     256

// scatter config
#define SC_CHUNK 2048
#define SC_NBLK  (NTOT/SC_CHUNK)   /* 2048 */
#define SC_L     (SC_CHUNK/TPB)    /* 8    */

// merge config
#define TILE     2048
#define PT       8                  /* TILE / TPB */

// scan config
#define SEG      4
#define SNSEG    (NTOT/SEG)        /* 1048576 */
#define SNBLK    (SNSEG/TPB)       /* 4096    */

typedef unsigned long long ull;

// ---------------- static device scratch ----------------
__device__ ull    g_key[NTOT];
__device__ ull    g_key2[NTOT];
__device__ float4 g_sorted[NTOT];            // {t, amp, y, diag} merged order
__device__ float2 g_DW[NTOT];
__device__ int    g_bcnt[SC_NBLK*NBANDS];
__device__ int    g_boff[SC_NBLK*NBANDS];
__device__ int    g_base[NBANDS+1];
__device__ float4 g_thrM[SNSEG];
__device__ double g_blkM[SNBLK*4], g_blkMex[SNBLK*4];
__device__ float2 g_thrA[SNSEG];
__device__ double g_blkA[SNBLK*2], g_blkAex[SNBLK*2];
__device__ double g_bsum[SNBLK];
__device__ float  g_amps[NBANDS], g_lags[NBANDS], g_ka, g_kc;

__device__ __forceinline__ unsigned fkey(float f){
    unsigned u = __float_as_uint(f);
    return (u & 0x80000000u) ? ~u : (u | 0x80000000u);
}
__device__ __forceinline__ float unfkey(unsigned k){
    unsigned u = (k & 0x80000000u) ? (k & 0x7fffffffu) : ~k;
    return __uint_as_float(u);
}

__device__ __forceinline__ void mmulD(double r[4], const double n[4], const double o[4]){
    double t0 = n[0]*o[0] + n[1]*o[2];
    double t1 = n[0]*o[1] + n[1]*o[3];
    double t2 = n[2]*o[0] + n[3]*o[2];
    double t3 = n[2]*o[1] + n[3]*o[3];
    double mx = fmax(fmax(fabs(t0),fabs(t1)), fmax(fabs(t2),fabs(t3)));
    double s  = (mx > 0.0) ? 1.0/mx : 1.0;
    r[0]=t0*s; r[1]=t1*s; r[2]=t2*s; r[3]=t3*s;
}

// ---------------- params ----------------
__global__ void k_init(const float* __restrict__ lad, const float* __restrict__ lg,
                       const float* __restrict__ lkp){
    if (threadIdx.x == 0){
        g_amps[0] = 1.f; g_lags[0] = 0.f;
        for (int b = 1; b < NBANDS; b++){
            g_amps[b] = expf(lad[b-1]);
            g_lags[b] = lg[b-1];
        }
        g_ka = expf(lkp[0]);
        g_kc = expf(lkp[1]);
    }
}

// ---------------- stage 1: histogram ----------------
__global__ void k_count(const int* __restrict__ band){
    __shared__ int sc[NBANDS];
    int tid = threadIdx.x;
    if (tid < NBANDS) sc[tid] = 0;
    __syncthreads();
    int cnt[NBANDS];
    #pragma unroll
    for (int b = 0; b < NBANDS; b++) cnt[b] = 0;
    int base = blockIdx.x * SC_CHUNK;
    for (int k = tid; k < SC_CHUNK; k += TPB) cnt[band[base+k]]++;
    #pragma unroll
    for (int b = 0; b < NBANDS; b++) if (cnt[b]) atomicAdd(&sc[b], cnt[b]);
    __syncthreads();
    if (tid < NBANDS) g_bcnt[blockIdx.x*NBANDS + tid] = sc[tid];
}

// exclusive prefix over band-major (b, blk): 16384 values
__global__ void k_offsets(){
    __shared__ int ssum[1024];
    int tid = threadIdx.x;
    int v[16];
    int run = 0;
    #pragma unroll
    for (int q = 0; q < 16; q++){
        int m = tid*16 + q;
        int b = m >> 11, blk = m & 2047;
        v[q] = run;
        run += g_bcnt[blk*NBANDS + b];
    }
    ssum[tid] = run;
    __syncthreads();
    for (int off = 1; off < 1024; off <<= 1){
        int pv = (tid >= off) ? ssum[tid-off] : 0;
        __syncthreads();
        ssum[tid] += pv;
        __syncthreads();
    }
    int excl = tid ? ssum[tid-1] : 0;
    #pragma unroll
    for (int q = 0; q < 16; q++){
        int m = tid*16 + q;
        int b = m >> 11, blk = m & 2047;
        int p = excl + v[q];
        g_boff[blk*NBANDS + b] = p;
        if (blk == 0) g_base[b] = p;
    }
    if (tid == 0) g_base[NBANDS] = NTOT;
}

// ---------------- stage 2: stable partition (keys only) ----------------
__global__ void k_scatter(const float* __restrict__ t, const int* __restrict__ band){
    __shared__ float s_t[SC_CHUNK];
    __shared__ int   s_b[SC_CHUNK];
    __shared__ int   s_scan[NBANDS*TPB];
    __shared__ float s_lag[NBANDS];
    int tid = threadIdx.x;
    int base = blockIdx.x * SC_CHUNK;
    if (tid < NBANDS) s_lag[tid] = g_lags[tid];
    for (int k = tid; k < SC_CHUNK; k += TPB){
        s_t[k] = t[base+k]; s_b[k] = band[base+k];
    }
    __syncthreads();
    int cnt[NBANDS];
    #pragma unroll
    for (int b = 0; b < NBANDS; b++) cnt[b] = 0;
    #pragma unroll
    for (int j = 0; j < SC_L; j++) cnt[s_b[tid*SC_L + j]]++;
    #pragma unroll
    for (int b = 0; b < NBANDS; b++) s_scan[b*TPB + tid] = cnt[b];
    __syncthreads();
    for (int off = 1; off < TPB; off <<= 1){
        int v[NBANDS];
        #pragma unroll
        for (int b = 0; b < NBANDS; b++) v[b] = (tid >= off) ? s_scan[b*TPB + tid - off] : 0;
        __syncthreads();
        #pragma unroll
        for (int b = 0; b < NBANDS; b++) s_scan[b*TPB + tid] += v[b];
        __syncthreads();
    }
    int pos[NBANDS];
    #pragma unroll
    for (int b = 0; b < NBANDS; b++)
        pos[b] = g_boff[blockIdx.x*NBANDS + b] + (tid ? s_scan[b*TPB + tid - 1] : 0);
    #pragma unroll
    for (int j = 0; j < SC_L; j++){
        int li = tid*SC_L + j;
        int b = s_b[li];
        float nt = s_t[li] - s_lag[b];
        // key = (orderable nt) << 32 | idx << 3 | band   (idx unique -> total order == (nt, idx))
        ull key = ((ull)fkey(nt) << 32) | ((ull)(unsigned)(base + li) << 3) | (unsigned)b;
        g_key[pos[b]++] = key;
    }
}

// ---------------- stage 3: merge-path pairwise merges ----------------
__device__ __forceinline__ int diag_g(const ull* __restrict__ A, int la,
                                      const ull* __restrict__ B, int lb, int k){
    int lo = k - lb; if (lo < 0) lo = 0;
    int hi = k < la ? k : la;
    while (lo < hi){
        int mid = (lo + hi) >> 1;
        if (__ldg(&A[mid]) < __ldg(&B[k-mid-1])) lo = mid + 1; else hi = mid;
    }
    return lo;
}

__global__ void k_merge(int r, int src_is_key){
    const ull* __restrict__ src = src_is_key ? g_key : g_key2;
    ull* __restrict__ dst       = src_is_key ? g_key2 : g_key;
    __shared__ ull sbuf[TILE];
    __shared__ int s_i0, s_i1;

    int p = blockIdx.y;
    int w = 1 << r;
    int aS = g_base[p*2*w], aE = g_base[p*2*w + w], bEnd = g_base[(p+1)*2*w];
    int la = aE - aS, lb = bEnd - aE;
    int psize = la + lb;
    int t0 = blockIdx.x * TILE;
    if (t0 >= psize) return;
    int t1 = t0 + TILE; if (t1 > psize) t1 = psize;
    int tsz = t1 - t0;

    const ull* A = src + aS;
    const ull* B = src + aE;

    if (threadIdx.x == 0) s_i0 = diag_g(A, la, B, lb, t0);
    if (threadIdx.x == 32) s_i1 = diag_g(A, la, B, lb, t1);
    __syncthreads();
    int i0 = s_i0, i1 = s_i1;
    int j0 = t0 - i0;
    int ai = i1 - i0;
    int bj = tsz - ai;

    for (int k = threadIdx.x; k < tsz; k += TPB)
        sbuf[k] = (k < ai) ? A[i0 + k] : B[j0 + k - ai];
    __syncthreads();

    int kloc = threadIdx.x * PT;
    int n = tsz - kloc; if (n > PT) n = PT;
    ull out[PT];
    if (n > 0){
        int lo = kloc - bj; if (lo < 0) lo = 0;
        int hi = kloc < ai ? kloc : ai;
        while (lo < hi){
            int mid = (lo + hi) >> 1;
            if (sbuf[mid] < sbuf[ai + kloc - mid - 1]) lo = mid + 1; else hi = mid;
        }
        int i = lo, j = kloc - lo;
        #pragma unroll
        for (int q = 0; q < PT; q++){
            if (q < n){
                bool ta = (j >= bj) || (i < ai && sbuf[i] < sbuf[ai + j]);
                out[q] = ta ? sbuf[i++] : sbuf[ai + j++];
            }
        }
    }
    __syncthreads();
    #pragma unroll
    for (int q = 0; q < PT; q++) if (q < n) sbuf[kloc + q] = out[q];
    __syncthreads();
    ull* D = dst + aS + t0;
    for (int k = threadIdx.x; k < tsz; k += TPB) D[k] = sbuf[k];
}

// ---------------- stage 4a: fused gather + S-scan segment reduce ----------------
__global__ void k_gsr(const float* __restrict__ y, const float* __restrict__ dg){
    __shared__ float sam[NBANDS];
    int tid = threadIdx.x;
    if (tid < NBANDS) sam[tid] = g_amps[tid];
    __syncthreads();
    int s = blockIdx.x * TPB + tid;
    int base = s * SEG;
    float a = g_ka, c = g_kc;

    ull kk[SEG];
    #pragma unroll
    for (int j = 0; j < SEG; j++) kk[j] = g_key2[base + j];
    float tprev = base ? unfkey((unsigned)(g_key2[base-1] >> 32)) : unfkey((unsigned)(kk[0] >> 32));

    float m0=1.f, m1=0.f, m2=0.f, m3=1.f;
    #pragma unroll
    for (int j = 0; j < SEG; j++){
        float nt  = unfkey((unsigned)(kk[j] >> 32));
        int   b   = (int)(kk[j] & 7u);
        int   idx = (int)((kk[j] >> 3) & 0x3FFFFFu);
        float amp = sam[b];
        float yy  = __ldg(&y[idx]);
        float dd  = __ldg(&dg[idx]);
        g_sorted[base + j] = make_float4(nt, amp, yy, dd);

        float dt = nt - tprev; tprev = nt;
        float phi2 = expf(-2.f*c*dt);
        float V = amp, U = a*amp;
        float A = dd + U*V;
        float e00 = (A - 2.f*U*V)*phi2, e01 = V*V, e10 = -U*U*phi2, e11 = A;
        float r0 = e00*m0 + e01*m2, r1 = e00*m1 + e01*m3;
        float r2 = e10*m0 + e11*m2, r3 = e10*m1 + e11*m3;
        float mx = fmaxf(fmaxf(fabsf(r0),fabsf(r1)), fmaxf(fabsf(r2),fabsf(r3)));
        float sc = (mx > 0.f) ? 1.f/mx : 1.f;
        m0=r0*sc; m1=r1*sc; m2=r2*sc; m3=r3*sc;
    }
    __shared__ double sm[TPB*4];
    sm[tid*4+0]=m0; sm[tid*4+1]=m1; sm[tid*4+2]=m2; sm[tid*4+3]=m3;
    __syncthreads();
    for (int off = 1; off < TPB; off <<= 1){
        double pv[4]; int h = (tid >= off);
        if (h){ for (int q=0;q<4;q++) pv[q] = sm[(tid-off)*4+q]; }
        __syncthreads();
        if (h){
            double cu[4]; for (int q=0;q<4;q++) cu[q] = sm[tid*4+q];
            double r[4]; mmulD(r, cu, pv);
            for (int q=0;q<4;q++) sm[tid*4+q] = r[q];
        }
        __syncthreads();
    }
    float4 ex;
    if (tid == 0){ ex = make_float4(1.f,0.f,0.f,1.f); }
    else { ex = make_float4((float)sm[(tid-1)*4+0],(float)sm[(tid-1)*4+1],
                            (float)sm[(tid-1)*4+2],(float)sm[(tid-1)*4+3]); }
    g_thrM[s] = ex;
    if (tid == TPB-1){ for (int q=0;q<4;q++) g_blkM[blockIdx.x*4+q] = sm[tid*4+q]; }
}

__global__ void k_blkscanM(){
    __shared__ double sm[1024*4];
    int tid = threadIdx.x;
    double cur[4] = {1.0,0.0,0.0,1.0};
    double p0[4],p1[4],p2[4],p3[4];
    double m[4];
    #define LOADM(i) { for(int q=0;q<4;q++) m[q]=g_blkM[(tid*4+(i))*4+q]; }
    LOADM(0); mmulD(p0, m, cur);
    LOADM(1); mmulD(p1, m, p0);
    LOADM(2); mmulD(p2, m, p1);
    LOADM(3); mmulD(p3, m, p2);
    #undef LOADM
    for (int q=0;q<4;q++) sm[tid*4+q] = p3[q];
    __syncthreads();
    for (int off = 1; off < 1024; off <<= 1){
        double pv[4]; int h = (tid >= off);
        if (h){ for (int q=0;q<4;q++) pv[q] = sm[(tid-off)*4+q]; }
        __syncthreads();
        if (h){
            double cu[4]; for (int q=0;q<4;q++) cu[q] = sm[tid*4+q];
            double r[4]; mmulD(r, cu, pv);
            for (int q=0;q<4;q++) sm[tid*4+q] = r[q];
        }
        __syncthreads();
    }
    double ex[4];
    if (tid == 0){ ex[0]=1.0; ex[1]=0.0; ex[2]=0.0; ex[3]=1.0; }
    else { for (int q=0;q<4;q++) ex[q] = sm[(tid-1)*4+q]; }
    double o0[4];
    for (int q=0;q<4;q++) g_blkMex[(tid*4+0)*4+q] = ex[q];
    mmulD(o0, p0, ex); for (int q=0;q<4;q++) g_blkMex[(tid*4+1)*4+q] = o0[q];
    mmulD(o0, p1, ex); for (int q=0;q<4;q++) g_blkMex[(tid*4+2)*4+q] = o0[q];
    mmulD(o0, p2, ex); for (int q=0;q<4;q++) g_blkMex[(tid*4+3)*4+q] = o0[q];
}

// ---------------- stage 4b: apply S, emit D/W, f-affine segments ----------------
__global__ void k_sapply(){
    int tid = threadIdx.x;
    int s = blockIdx.x * TPB + tid;
    int base = s * SEG;
    float4 Ptf = g_thrM[s];
    double Pt[4] = {(double)Ptf.x,(double)Ptf.y,(double)Ptf.z,(double)Ptf.w};
    double Pb[4];
    for (int q=0;q<4;q++) Pb[q] = g_blkMex[blockIdx.x*4+q];
    double E[4]; mmulD(E, Pt, Pb);
    float Sp = (float)(E[1] / E[3]);

    float a = g_ka, c = g_kc;
    float4 e[SEG];
    #pragma unroll
    for (int j = 0; j < SEG; j++) e[j] = g_sorted[base + j];
    float tprev = base ? g_sorted[base-1].x : e[0].x;
    float al = 1.f, be = 0.f;
    #pragma unroll
    for (int j = 0; j < SEG; j++){
        float dt = e[j].x - tprev;
        tprev = e[j].x;
        float phi = expf(-c*dt);
        float phi2 = phi*phi;
        float V = e[j].y, U = a*V;
        float A = e[j].w + U*V;
        float S = phi2 * Sp;
        float D = A - U*U*S;
        float W = (V - U*S) / D;
        g_DW[base+j] = make_float2(D, W);
        float an = phi * (1.f - W*U);
        float bn = W * e[j].z;
        be = an*be + bn;
        al *= an;
        Sp = S + D*W*W;
    }
    __shared__ double sa[TPB*2];
    sa[tid*2] = (double)al; sa[tid*2+1] = (double)be;
    __syncthreads();
    for (int off = 1; off < TPB; off <<= 1){
        double pa=0.0, pb=0.0; int h = (tid >= off);
        if (h){ pa = sa[(tid-off)*2]; pb = sa[(tid-off)*2+1]; }
        __syncthreads();
        if (h){
            double ca = sa[tid*2], cb = sa[tid*2+1];
            sa[tid*2] = ca*pa; sa[tid*2+1] = ca*pb + cb;
        }
        __syncthreads();
    }
    if (tid == 0) g_thrA[s] = make_float2(1.f, 0.f);
    else          g_thrA[s] = make_float2((float)sa[(tid-1)*2], (float)sa[(tid-1)*2+1]);
    if (tid == TPB-1){ g_blkA[blockIdx.x*2] = sa[tid*2]; g_blkA[blockIdx.x*2+1] = sa[tid*2+1]; }
}

__global__ void k_blkscanA(){
    __shared__ double sa[1024*2];
    int tid = threadIdx.x;
    double pa0,pb0,pa1,pb1,pa2,pb2,pa3,pb3;
    {
        double ca = g_blkA[(tid*4+0)*2], cb = g_blkA[(tid*4+0)*2+1];
        pa0 = ca; pb0 = cb;
        ca = g_blkA[(tid*4+1)*2]; cb = g_blkA[(tid*4+1)*2+1];
        pa1 = ca*pa0; pb1 = ca*pb0 + cb;
        ca = g_blkA[(tid*4+2)*2]; cb = g_blkA[(tid*4+2)*2+1];
        pa2 = ca*pa1; pb2 = ca*pb1 + cb;
        ca = g_blkA[(tid*4+3)*2]; cb = g_blkA[(tid*4+3)*2+1];
        pa3 = ca*pa2; pb3 = ca*pb2 + cb;
    }
    sa[tid*2] = pa3; sa[tid*2+1] = pb3;
    __syncthreads();
    for (int off = 1; off < 1024; off <<= 1){
        double pa=0.0, pb=0.0; int h = (tid >= off);
        if (h){ pa = sa[(tid-off)*2]; pb = sa[(tid-off)*2+1]; }
        __syncthreads();
        if (h){
            double ca = sa[tid*2], cb = sa[tid*2+1];
            sa[tid*2] = ca*pa; sa[tid*2+1] = ca*pb + cb;
        }
        __syncthreads();
    }
    double exa, exb;
    if (tid == 0){ exa = 1.0; exb = 0.0; }
    else { exa = sa[(tid-1)*2]; exb = sa[(tid-1)*2+1]; }
    g_blkAex[(tid*4+0)*2] = exa;        g_blkAex[(tid*4+0)*2+1] = exb;
    g_blkAex[(tid*4+1)*2] = pa0*exa;    g_blkAex[(tid*4+1)*2+1] = pa0*exb + pb0;
    g_blkAex[(tid*4+2)*2] = pa1*exa;    g_blkAex[(tid*4+2)*2+1] = pa1*exb + pb1;
    g_blkAex[(tid*4+3)*2] = pa2*exa;    g_blkAex[(tid*4+3)*2+1] = pa2*exb + pb2;
}

// ---------------- stage 4c: apply f, compute z, reduce ----------------
__global__ void k_fapply(){
    int tid = threadIdx.x;
    int s = blockIdx.x * TPB + tid;
    int base = s * SEG;
    float2 ta = g_thrA[s];
    float fb = (float)g_blkAex[blockIdx.x*2+1];
    float f = ta.x * fb + ta.y;
    float a = g_ka, c = g_kc;
    float4 e[SEG];
    #pragma unroll
    for (int j = 0; j < SEG; j++) e[j] = g_sorted[base + j];
    float2 dw[SEG];
    #pragma unroll
    for (int j = 0; j < SEG; j++) dw[j] = g_DW[base + j];
    float tprev = base ? g_sorted[base-1].x : e[0].x;
    double loc = 0.0;
    #pragma unroll
    for (int j = 0; j < SEG; j++){
        float dt = e[j].x - tprev;
        tprev = e[j].x;
        float phi = expf(-c*dt);
        float U = a * e[j].y;
        float fin = phi * f;
        float z = e[j].z - U * fin;
        f = fin + dw[j].y * z;
        loc += (double)(z*z / dw[j].x) + (double)logf(dw[j].x);
    }
    __shared__ double red[TPB];
    red[tid] = loc;
    __syncthreads();
    for (int off = TPB/2; off > 0; off >>= 1){
        if (tid < off) red[tid] += red[tid+off];
        __syncthreads();
    }
    if (tid == 0) g_bsum[blockIdx.x] = red[0];
}

__global__ void k_final(float* out){
    __shared__ double red[1024];
    int tid = threadIdx.x;
    double s = 0.0;
    #pragma unroll
    for (int q = 0; q < 4; q++) s += g_bsum[tid*4 + q];
    red[tid] = s;
    __syncthreads();
    for (int off = 512; off > 0; off >>= 1){
        if (tid < off) red[tid] += red[tid+off];
        __syncthreads();
    }
    if (tid == 0) out[0] = (float)(0.5 * (red[0] + (double)NTOT * 1.8378770664093454));
}

// ---------------- launch ----------------
extern "C" void kernel_launch(void* const* d_in, const int* in_sizes, int n_in,
                              void* d_out, int out_size){
    const float* t    = (const float*)d_in[0];
    const int*   band = (const int*)  d_in[1];
    const float* y    = (const float*)d_in[2];
    const float* dg   = (const float*)d_in[3];
    const float* lad  = (const float*)d_in[4];
    const float* lg   = (const float*)d_in[5];
    const float* lkp  = (const float*)d_in[6];
    float* out = (float*)d_out;

    k_init    <<<1, 32>>>(lad, lg, lkp);
    k_count   <<<SC_NBLK, TPB>>>(band);
    k_offsets <<<1, 1024>>>();
    k_scatter <<<SC_NBLK, TPB>>>(t, band);

    // merge rounds: 8 -> 4 -> 2 -> 1 lists
    {
        int tpp0 = (NTOT/4)/TILE + 2;   // round 0: 4 pairs
        int tpp1 = (NTOT/2)/TILE + 2;   // round 1: 2 pairs
        int tpp2 = (NTOT/1)/TILE + 1;   // round 2: 1 pair
        k_merge<<<dim3(tpp0, 4), TPB>>>(0, 1);  // g_key  -> g_key2
        k_merge<<<dim3(tpp1, 2), TPB>>>(1, 0);  // g_key2 -> g_key
        k_merge<<<dim3(tpp2, 1), TPB>>>(2, 1);  // g_key  -> g_key2
    }

    k_gsr     <<<SNBLK, TPB>>>(y, dg);
    k_blkscanM<<<1, 1024>>>();
    k_sapply  <<<SNBLK, TPB>>>();
    k_blkscanA<<<1, 1024>>>();
    k_fapply  <<<SNBLK, TPB>>>();
    k_final   <<<1, 1024>>>(out);
}

// round 4
// speedup vs baseline: 1.9681x; 1.3941x over previous
#include <cuda_runtime.h>
#include <stdint.h>
#include <math.h>

#define NTOT    (1<<22)
#define NBANDS  8
#define TPB     256

// scatter config
#define SC_CHUNK 2048
#define SC_NBLK  (NTOT/SC_CHUNK)   /* 2048 */
#define SC_L     (SC_CHUNK/TPB)    /* 8    */

// merge / tile config
#define TILE     2048
#define PT       8                  /* TILE / TPB */
#define NTILE    (NTOT/TILE)        /* 2048 */
#define NSEG     (NTILE*TPB)        /* 524288 segments of 8 */

typedef unsigned long long ull;

// ---------------- static device scratch ----------------
__device__ ull    g_key[NTOT];
__device__ ull    g_key2[NTOT];
__device__ float4 g_sorted[NTOT];            // {t, amp, y, diag} merged order
__device__ int    g_bcnt[SC_NBLK*NBANDS];
__device__ int    g_boff[SC_NBLK*NBANDS];
__device__ int    g_base[NBANDS+1];
__device__ float4 g_thrM[NSEG];              // exclusive-in-tile segment matrices
__device__ double g_blkM[NTILE*4], g_blkMex[NTILE*4];
__device__ float2 g_thrA[NSEG];
__device__ double g_blkA[NTILE*2], g_blkAex[NTILE*2];
__device__ double g_bsum[NTILE];
__device__ float  g_amps[NBANDS], g_lags[NBANDS], g_ka, g_kc;

__device__ __forceinline__ unsigned fkey(float f){
    unsigned u = __float_as_uint(f);
    return (u & 0x80000000u) ? ~u : (u | 0x80000000u);
}
__device__ __forceinline__ float unfkey(unsigned k){
    unsigned u = (k & 0x80000000u) ? (k & 0x7fffffffu) : ~k;
    return __uint_as_float(u);
}

__device__ __forceinline__ void mmulD(double r[4], const double n[4], const double o[4]){
    double t0 = n[0]*o[0] + n[1]*o[2];
    double t1 = n[0]*o[1] + n[1]*o[3];
    double t2 = n[2]*o[0] + n[3]*o[2];
    double t3 = n[2]*o[1] + n[3]*o[3];
    double mx = fmax(fmax(fabs(t0),fabs(t1)), fmax(fabs(t2),fabs(t3)));
    double s  = (mx > 0.0) ? 1.0/mx : 1.0;
    r[0]=t0*s; r[1]=t1*s; r[2]=t2*s; r[3]=t3*s;
}

// ---------------- params ----------------
__global__ void k_init(const float* __restrict__ lad, const float* __restrict__ lg,
                       const float* __restrict__ lkp){
    if (threadIdx.x == 0){
        g_amps[0] = 1.f; g_lags[0] = 0.f;
        for (int b = 1; b < NBANDS; b++){
            g_amps[b] = expf(lad[b-1]);
            g_lags[b] = lg[b-1];
        }
        g_ka = expf(lkp[0]);
        g_kc = expf(lkp[1]);
    }
}

// ---------------- stage 1: histogram ----------------
__global__ void k_count(const int* __restrict__ band){
    __shared__ int sc[NBANDS];
    int tid = threadIdx.x;
    if (tid < NBANDS) sc[tid] = 0;
    __syncthreads();
    int cnt[NBANDS];
    #pragma unroll
    for (int b = 0; b < NBANDS; b++) cnt[b] = 0;
    int base = blockIdx.x * SC_CHUNK;
    for (int k = tid; k < SC_CHUNK; k += TPB) cnt[band[base+k]]++;
    #pragma unroll
    for (int b = 0; b < NBANDS; b++) if (cnt[b]) atomicAdd(&sc[b], cnt[b]);
    __syncthreads();
    if (tid < NBANDS) g_bcnt[blockIdx.x*NBANDS + tid] = sc[tid];
}

// exclusive prefix over band-major (b, blk): 16384 values
__global__ void k_offsets(){
    __shared__ int ssum[1024];
    int tid = threadIdx.x;
    int v[16];
    int run = 0;
    #pragma unroll
    for (int q = 0; q < 16; q++){
        int m = tid*16 + q;
        int b = m >> 11, blk = m & 2047;
        v[q] = run;
        run += g_bcnt[blk*NBANDS + b];
    }
    ssum[tid] = run;
    __syncthreads();
    for (int off = 1; off < 1024; off <<= 1){
        int pv = (tid >= off) ? ssum[tid-off] : 0;
        __syncthreads();
        ssum[tid] += pv;
        __syncthreads();
    }
    int excl = tid ? ssum[tid-1] : 0;
    #pragma unroll
    for (int q = 0; q < 16; q++){
        int m = tid*16 + q;
        int b = m >> 11, blk = m & 2047;
        int p = excl + v[q];
        g_boff[blk*NBANDS + b] = p;
        if (blk == 0) g_base[b] = p;
    }
    if (tid == 0) g_base[NBANDS] = NTOT;
}

// ---------------- stage 2: stable partition (keys only) ----------------
__global__ void k_scatter(const float* __restrict__ t, const int* __restrict__ band){
    __shared__ float s_t[SC_CHUNK];
    __shared__ int   s_b[SC_CHUNK];
    __shared__ int   s_scan[NBANDS*TPB];
    __shared__ float s_lag[NBANDS];
    int tid = threadIdx.x;
    int base = blockIdx.x * SC_CHUNK;
    if (tid < NBANDS) s_lag[tid] = g_lags[tid];
    for (int k = tid; k < SC_CHUNK; k += TPB){
        s_t[k] = t[base+k]; s_b[k] = band[base+k];
    }
    __syncthreads();
    int cnt[NBANDS];
    #pragma unroll
    for (int b = 0; b < NBANDS; b++) cnt[b] = 0;
    #pragma unroll
    for (int j = 0; j < SC_L; j++) cnt[s_b[tid*SC_L + j]]++;
    #pragma unroll
    for (int b = 0; b < NBANDS; b++) s_scan[b*TPB + tid] = cnt[b];
    __syncthreads();
    for (int off = 1; off < TPB; off <<= 1){
        int v[NBANDS];
        #pragma unroll
        for (int b = 0; b < NBANDS; b++) v[b] = (tid >= off) ? s_scan[b*TPB + tid - off] : 0;
        __syncthreads();
        #pragma unroll
        for (int b = 0; b < NBANDS; b++) s_scan[b*TPB + tid] += v[b];
        __syncthreads();
    }
    int pos[NBANDS];
    #pragma unroll
    for (int b = 0; b < NBANDS; b++)
        pos[b] = g_boff[blockIdx.x*NBANDS + b] + (tid ? s_scan[b*TPB + tid - 1] : 0);
    #pragma unroll
    for (int j = 0; j < SC_L; j++){
        int li = tid*SC_L + j;
        int b = s_b[li];
        float nt = s_t[li] - s_lag[b];
        ull key = ((ull)fkey(nt) << 32) | ((ull)(unsigned)(base + li) << 3) | (unsigned)b;
        g_key[pos[b]++] = key;
    }
}

// ---------------- merge-path helpers ----------------
__device__ __forceinline__ int diag_g(const ull* __restrict__ A, int la,
                                      const ull* __restrict__ B, int lb, int k){
    int lo = k - lb; if (lo < 0) lo = 0;
    int hi = k < la ? k : la;
    while (lo < hi){
        int mid = (lo + hi) >> 1;
        if (__ldg(&A[mid]) < __ldg(&B[k-mid-1])) lo = mid + 1; else hi = mid;
    }
    return lo;
}

// generic pairwise merge (rounds 0 and 1)
__global__ void k_merge(int r, int src_is_key){
    const ull* __restrict__ src = src_is_key ? g_key : g_key2;
    ull* __restrict__ dst       = src_is_key ? g_key2 : g_key;
    __shared__ ull sbuf[TILE];
    __shared__ int s_i0, s_i1;

    int p = blockIdx.y;
    int w = 1 << r;
    int aS = g_base[p*2*w], aE = g_base[p*2*w + w], bEnd = g_base[(p+1)*2*w];
    int la = aE - aS, lb = bEnd - aE;
    int psize = la + lb;
    int t0 = blockIdx.x * TILE;
    if (t0 >= psize) return;
    int t1 = t0 + TILE; if (t1 > psize) t1 = psize;
    int tsz = t1 - t0;

    const ull* A = src + aS;
    const ull* B = src + aE;

    if (threadIdx.x == 0)  s_i0 = diag_g(A, la, B, lb, t0);
    if (threadIdx.x == 32) s_i1 = diag_g(A, la, B, lb, t1);
    __syncthreads();
    int i0 = s_i0, i1 = s_i1;
    int j0 = t0 - i0;
    int ai = i1 - i0;
    int bj = tsz - ai;

    for (int k = threadIdx.x; k < tsz; k += TPB)
        sbuf[k] = (k < ai) ? A[i0 + k] : B[j0 + k - ai];
    __syncthreads();

    int kloc = threadIdx.x * PT;
    int n = tsz - kloc; if (n > PT) n = PT; if (n < 0) n = 0;
    ull out[PT];
    if (n > 0){
        int lo = kloc - bj; if (lo < 0) lo = 0;
        int hi = kloc < ai ? kloc : ai;
        while (lo < hi){
            int mid = (lo + hi) >> 1;
            if (sbuf[mid] < sbuf[ai + kloc - mid - 1]) lo = mid + 1; else hi = mid;
        }
        int i = lo, j = kloc - lo;
        #pragma unroll
        for (int q = 0; q < PT; q++){
            if (q < n){
                bool ta = (j >= bj) || (i < ai && sbuf[i] < sbuf[ai + j]);
                out[q] = ta ? sbuf[i++] : sbuf[ai + j++];
            }
        }
    }
    __syncthreads();
    #pragma unroll
    for (int q = 0; q < PT; q++) if (q < n) sbuf[kloc + q] = out[q];
    __syncthreads();
    ull* D = dst + aS + t0;
    for (int k = threadIdx.x; k < tsz; k += TPB) D[k] = sbuf[k];
}

// ---------------- fused final merge + gather + S-matrix reduce ----------------
__global__ void k_mgsr(const float* __restrict__ y, const float* __restrict__ dg){
    __shared__ __align__(16) char raw[TILE*16];      // union: ull[TILE] then float4[TILE]
    ull*    sbuf = (ull*)raw;
    float4* sf4  = (float4*)raw;
    __shared__ double sm[TPB*4];
    __shared__ int s_i0, s_i1;
    __shared__ float sam[NBANDS];
    int tid = threadIdx.x;
    if (tid < NBANDS) sam[tid] = g_amps[tid];

    int aE = g_base[4];
    int la = aE, lb = NTOT - aE;
    const ull* A = g_key;
    const ull* B = g_key + aE;
    int t0 = blockIdx.x * TILE;
    if (tid == 0)  s_i0 = diag_g(A, la, B, lb, t0);
    if (tid == 32) s_i1 = diag_g(A, la, B, lb, t0 + TILE);
    __syncthreads();
    int i0 = s_i0, i1 = s_i1, j0 = t0 - i0;
    int ai = i1 - i0, bj = TILE - ai;

    ull kprev = 0;
    if (t0 > 0){
        ull ca = (i0 > 0) ? __ldg(&A[i0-1]) : 0ULL;
        ull cb = (j0 > 0) ? __ldg(&B[j0-1]) : 0ULL;
        kprev = ca > cb ? ca : cb;
    }

    for (int k = tid; k < TILE; k += TPB)
        sbuf[k] = (k < ai) ? A[i0 + k] : B[j0 + k - ai];
    __syncthreads();

    int kloc = tid * PT;
    int lo = kloc - bj; if (lo < 0) lo = 0;
    int hi = kloc < ai ? kloc : ai;
    while (lo < hi){
        int mid = (lo + hi) >> 1;
        if (sbuf[mid] < sbuf[ai + kloc - mid - 1]) lo = mid + 1; else hi = mid;
    }
    int i = lo, j = kloc - lo;
    ull out[PT];
    #pragma unroll
    for (int q = 0; q < PT; q++){
        bool ta = (j >= bj) || (i < ai && sbuf[i] < sbuf[ai + j]);
        out[q] = ta ? sbuf[i++] : sbuf[ai + j++];
    }
    __syncthreads();
    #pragma unroll
    for (int q = 0; q < PT; q++) sbuf[kloc + q] = out[q];
    __syncthreads();
    ull pk = (kloc == 0) ? (t0 ? kprev : sbuf[0]) : sbuf[kloc-1];
    __syncthreads();   // all neighbor reads done; raw now reusable as sf4

    float tprev = unfkey((unsigned)(pk >> 32));
    float a = g_ka, c = g_kc;
    float m0=1.f, m1=0.f, m2=0.f, m3=1.f;
    #pragma unroll
    for (int q = 0; q < PT; q++){
        ull kk = out[q];
        float nt  = unfkey((unsigned)(kk >> 32));
        int   b   = (int)(kk & 7u);
        int   idx = (int)((kk >> 3) & 0x3FFFFFu);
        float amp = sam[b];
        float yy  = __ldg(&y[idx]);
        float dd  = __ldg(&dg[idx]);
        sf4[kloc + q] = make_float4(nt, amp, yy, dd);

        float dt = nt - tprev; tprev = nt;
        float phi2 = expf(-2.f*c*dt);
        float V = amp, U = a*amp;
        float Am = dd + U*V;
        float e00 = (Am - 2.f*U*V)*phi2, e01 = V*V, e10 = -U*U*phi2, e11 = Am;
        float r0 = e00*m0 + e01*m2, r1 = e00*m1 + e01*m3;
        float r2 = e10*m0 + e11*m2, r3 = e10*m1 + e11*m3;
        float mx = fmaxf(fmaxf(fabsf(r0),fabsf(r1)), fmaxf(fabsf(r2),fabsf(r3)));
        float sc = (mx > 0.f) ? 1.f/mx : 1.f;
        m0=r0*sc; m1=r1*sc; m2=r2*sc; m3=r3*sc;
    }
    sm[tid*4+0]=m0; sm[tid*4+1]=m1; sm[tid*4+2]=m2; sm[tid*4+3]=m3;
    __syncthreads();
    for (int off = 1; off < TPB; off <<= 1){
        double pv[4]; int h = (tid >= off);
        if (h){ for (int q=0;q<4;q++) pv[q] = sm[(tid-off)*4+q]; }
        __syncthreads();
        if (h){
            double cu[4]; for (int q=0;q<4;q++) cu[q] = sm[tid*4+q];
            double r[4]; mmulD(r, cu, pv);
            for (int q=0;q<4;q++) sm[tid*4+q] = r[q];
        }
        __syncthreads();
    }
    float4 ex;
    if (tid == 0) ex = make_float4(1.f,0.f,0.f,1.f);
    else ex = make_float4((float)sm[(tid-1)*4+0],(float)sm[(tid-1)*4+1],
                          (float)sm[(tid-1)*4+2],(float)sm[(tid-1)*4+3]);
    g_thrM[blockIdx.x*TPB + tid] = ex;
    if (tid == TPB-1){ for (int q=0;q<4;q++) g_blkM[blockIdx.x*4+q] = sm[tid*4+q]; }

    for (int k = tid; k < TILE; k += TPB) g_sorted[t0 + k] = sf4[k];
}

// ---------------- tile-matrix exclusive scan (2048 tiles, 1024 thr x2) ----------------
__global__ void k_blkscanM(){
    __shared__ double sm[1024*4];
    int tid = threadIdx.x;
    double p0[4], p1[4], m[4];
    for (int q=0;q<4;q++) p0[q] = g_blkM[(tid*2+0)*4+q];
    for (int q=0;q<4;q++) m[q]  = g_blkM[(tid*2+1)*4+q];
    mmulD(p1, m, p0);
    for (int q=0;q<4;q++) sm[tid*4+q] = p1[q];
    __syncthreads();
    for (int off = 1; off < 1024; off <<= 1){
        double pv[4]; int h = (tid >= off);
        if (h){ for (int q=0;q<4;q++) pv[q] = sm[(tid-off)*4+q]; }
        __syncthreads();
        if (h){
            double cu[4]; for (int q=0;q<4;q++) cu[q] = sm[tid*4+q];
            double r[4]; mmulD(r, cu, pv);
            for (int q=0;q<4;q++) sm[tid*4+q] = r[q];
        }
        __syncthreads();
    }
    double ex[4];
    if (tid == 0){ ex[0]=1.0; ex[1]=0.0; ex[2]=0.0; ex[3]=1.0; }
    else { for (int q=0;q<4;q++) ex[q] = sm[(tid-1)*4+q]; }
    for (int q=0;q<4;q++) g_blkMex[(tid*2+0)*4+q] = ex[q];
    double o[4]; mmulD(o, p0, ex);
    for (int q=0;q<4;q++) g_blkMex[(tid*2+1)*4+q] = o[q];
}

// ---------------- apply S, build f-affine (no DW store) ----------------
__global__ void k_sapply(){
    __shared__ __align__(16) float4 sf4[TILE];
    __shared__ double sa[TPB*2];
    __shared__ float s_pv;
    int tid = threadIdx.x, blk = blockIdx.x;
    int t0 = blk * TILE;
    float pvg = 0.f;
    if (tid == 0 && t0 > 0) pvg = g_sorted[t0-1].x;
    for (int k = tid; k < TILE; k += TPB) sf4[k] = g_sorted[t0 + k];
    __syncthreads();
    if (tid == 0) s_pv = (t0 > 0) ? pvg : sf4[0].x;
    __syncthreads();

    float4 mf = g_thrM[blk*TPB + tid];
    double Pt[4] = {(double)mf.x,(double)mf.y,(double)mf.z,(double)mf.w};
    double Pb[4]; for (int q=0;q<4;q++) Pb[q] = g_blkMex[blk*4+q];
    double E[4]; mmulD(E, Pt, Pb);
    float Sp = (float)(E[1] / E[3]);

    int kloc = tid * PT;
    float tprev = kloc ? sf4[kloc-1].x : s_pv;
    float a = g_ka, c = g_kc;
    float al = 1.f, be = 0.f;
    #pragma unroll
    for (int q = 0; q < PT; q++){
        float4 e = sf4[kloc+q];
        float dt = e.x - tprev; tprev = e.x;
        float phi = expf(-c*dt);
        float phi2 = phi*phi;
        float V = e.y, U = a*V;
        float Am = e.w + U*V;
        float S = phi2 * Sp;
        float D = Am - U*U*S;
        float W = (V - U*S) / D;
        float an = phi * (1.f - W*U);
        float bn = W * e.z;
        be = an*be + bn;
        al *= an;
        Sp = S + D*W*W;
    }
    sa[tid*2] = (double)al; sa[tid*2+1] = (double)be;
    __syncthreads();
    for (int off = 1; off < TPB; off <<= 1){
        double pa=0.0, pb=0.0; int h = (tid >= off);
        if (h){ pa = sa[(tid-off)*2]; pb = sa[(tid-off)*2+1]; }
        __syncthreads();
        if (h){
            double ca = sa[tid*2], cb = sa[tid*2+1];
            sa[tid*2] = ca*pa; sa[tid*2+1] = ca*pb + cb;
        }
        __syncthreads();
    }
    if (tid == 0) g_thrA[blk*TPB + tid] = make_float2(1.f, 0.f);
    else          g_thrA[blk*TPB + tid] = make_float2((float)sa[(tid-1)*2], (float)sa[(tid-1)*2+1]);
    if (tid == TPB-1){ g_blkA[blk*2] = sa[tid*2]; g_blkA[blk*2+1] = sa[tid*2+1]; }
}

__global__ void k_blkscanA(){
    __shared__ double sa[1024*2];
    int tid = threadIdx.x;
    double pa0 = g_blkA[(tid*2+0)*2], pb0 = g_blkA[(tid*2+0)*2+1];
    double ca  = g_blkA[(tid*2+1)*2], cb  = g_blkA[(tid*2+1)*2+1];
    double pa1 = ca*pa0, pb1 = ca*pb0 + cb;
    sa[tid*2] = pa1; sa[tid*2+1] = pb1;
    __syncthreads();
    for (int off = 1; off < 1024; off <<= 1){
        double pa=0.0, pb=0.0; int h = (tid >= off);
        if (h){ pa = sa[(tid-off)*2]; pb = sa[(tid-off)*2+1]; }
        __syncthreads();
        if (h){
            double c2 = sa[tid*2], d2 = sa[tid*2+1];
            sa[tid*2] = c2*pa; sa[tid*2+1] = c2*pb + d2;
        }
        __syncthreads();
    }
    double exa, exb;
    if (tid == 0){ exa = 1.0; exb = 0.0; }
    else { exa = sa[(tid-1)*2]; exb = sa[(tid-1)*2+1]; }
    g_blkAex[(tid*2+0)*2] = exa;      g_blkAex[(tid*2+0)*2+1] = exb;
    g_blkAex[(tid*2+1)*2] = pa0*exa;  g_blkAex[(tid*2+1)*2+1] = pa0*exb + pb0;
}

// ---------------- apply f, recompute D/W, accumulate ----------------
__global__ void k_fapply(){
    __shared__ __align__(16) float4 sf4[TILE];
    __shared__ double red[TPB];
    __shared__ float s_pv;
    int tid = threadIdx.x, blk = blockIdx.x;
    int t0 = blk * TILE;
    float pvg = 0.f;
    if (tid == 0 && t0 > 0) pvg = g_sorted[t0-1].x;
    for (int k = tid; k < TILE; k += TPB) sf4[k] = g_sorted[t0 + k];
    __syncthreads();
    if (tid == 0) s_pv = (t0 > 0) ? pvg : sf4[0].x;
    __syncthreads();

    float4 mf = g_thrM[blk*TPB + tid];
    double Pt[4] = {(double)mf.x,(double)mf.y,(double)mf.z,(double)mf.w};
    double Pb[4]; for (int q=0;q<4;q++) Pb[q] = g_blkMex[blk*4+q];
    double E[4]; mmulD(E, Pt, Pb);
    float Sp = (float)(E[1] / E[3]);

    float2 ta = g_thrA[blk*TPB + tid];
    float fb = (float)g_blkAex[blk*2+1];
    float f = ta.x * fb + ta.y;

    int kloc = tid * PT;
    float tprev = kloc ? sf4[kloc-1].x : s_pv;
    float a = g_ka, c = g_kc;
    double loc = 0.0;
    #pragma unroll
    for (int q = 0; q < PT; q++){
        float4 e = sf4[kloc+q];
        float dt = e.x - tprev; tprev = e.x;
        float phi = expf(-c*dt);
        float phi2 = phi*phi;
        float V = e.y, U = a*V;
        float Am = e.w + U*V;
        float S = phi2 * Sp;
        float D = Am - U*U*S;
        float W = (V - U*S) / D;
        float fin = phi * f;
        float z = e.z - U * fin;
        f = fin + W * z;
        Sp = S + D*W*W;
        loc += (double)(z*z / D) + (double)logf(D);
    }
    red[tid] = loc;
    __syncthreads();
    for (int off = TPB/2; off > 0; off >>= 1){
        if (tid < off) red[tid] += red[tid+off];
        __syncthreads();
    }
    if (tid == 0) g_bsum[blk] = red[0];
}

__global__ void k_final(float* out){
    __shared__ double red[1024];
    int tid = threadIdx.x;
    double s = g_bsum[tid*2] + g_bsum[tid*2+1];
    red[tid] = s;
    __syncthreads();
    for (int off = 512; off > 0; off >>= 1){
        if (tid < off) red[tid] += red[tid+off];
        __syncthreads();
    }
    if (tid == 0) out[0] = (float)(0.5 * (red[0] + (double)NTOT * 1.8378770664093454));
}

// ---------------- launch ----------------
extern "C" void kernel_launch(void* const* d_in, const int* in_sizes, int n_in,
                              void* d_out, int out_size){
    const float* t    = (const float*)d_in[0];
    const int*   band = (const int*)  d_in[1];
    const float* y    = (const float*)d_in[2];
    const float* dg   = (const float*)d_in[3];
    const float* lad  = (const float*)d_in[4];
    const float* lg   = (const float*)d_in[5];
    const float* lkp  = (const float*)d_in[6];
    float* out = (float*)d_out;

    k_init    <<<1, 32>>>(lad, lg, lkp);
    k_count   <<<SC_NBLK, TPB>>>(band);
    k_offsets <<<1, 1024>>>();
    k_scatter <<<SC_NBLK, TPB>>>(t, band);

    // merge rounds: 8 -> 4 (key->key2), 4 -> 2 (key2->key), then fused final merge
    {
        int tpp0 = (NTOT/4)/TILE + 2;
        int tpp1 = (NTOT/2)/TILE + 2;
        k_merge<<<dim3(tpp0, 4), TPB>>>(0, 1);
        k_merge<<<dim3(tpp1, 2), TPB>>>(1, 0);
    }
    k_mgsr    <<<NTILE, TPB>>>(y, dg);
    k_blkscanM<<<1, 1024>>>();
    k_sapply  <<<NTILE, TPB>>>();
    k_blkscanA<<<1, 1024>>>();
    k_fapply  <<<NTILE, TPB>>>();
    k_final   <<<1, 1024>>>(out);
}